// round 1
// baseline (speedup 1.0000x reference)
#include <cuda_runtime.h>
#include <cuda_bf16.h>
#include <cstdint>

// Sparse average pooling:
//   out[rules_out[r], :] += input[rules_in[r], :] * (1/8)
// C = 64 floats per row. 16 threads cooperate on one rule (one float4 each).
// Scatter uses red.global.add.v4.f32 (sm_90+) to cut atomic op count 4x.

__global__ void avgpool_scatter_kernel(
    const float* __restrict__ input,     // [n_in, 64]
    const int*   __restrict__ rules_in,  // [n_rules]
    const int*   __restrict__ rules_out, // [n_rules]
    float*       __restrict__ out,       // [n_out, 64]
    int n_rules)
{
    const float scale = 0.125f;  // 1 / POOL_VOLUME (2*2*2)

    long long gid = (long long)blockIdx.x * blockDim.x + threadIdx.x;
    long long total = (long long)n_rules * 16;
    if (gid >= total) return;

    int r = (int)(gid >> 4);     // rule index
    int c = (int)(gid & 15);     // float4 column chunk (0..15)

    int rin  = rules_in[r];
    int rout = rules_out[r];

    const float4* src = reinterpret_cast<const float4*>(input + (long long)rin * 64) + c;
    float4 v = *src;
    v.x *= scale; v.y *= scale; v.z *= scale; v.w *= scale;

    float* dst = out + (long long)rout * 64 + c * 4;
    asm volatile(
        "red.global.add.v4.f32 [%0], {%1, %2, %3, %4};"
        :: "l"(dst), "f"(v.x), "f"(v.y), "f"(v.z), "f"(v.w)
        : "memory");
}

extern "C" void kernel_launch(void* const* d_in, const int* in_sizes, int n_in,
                              void* d_out, int out_size)
{
    const float* input     = (const float*)d_in[0];
    const int*   rules_in  = (const int*)d_in[1];
    const int*   rules_out = (const int*)d_in[2];
    // d_in[3] is the scalar n_out; out_size already encodes n_out * 64.
    float* out = (float*)d_out;

    int n_rules = in_sizes[1];  // rules_in element count

    // Zero-initialize output (d_out is poisoned before timing).
    cudaMemsetAsync(out, 0, (size_t)out_size * sizeof(float));

    long long total = (long long)n_rules * 16;
    int threads = 256;
    long long blocks = (total + threads - 1) / threads;
    avgpool_scatter_kernel<<<(unsigned)blocks, threads>>>(
        input, rules_in, rules_out, out, n_rules);
}

// round 2
// speedup vs baseline: 1.2322x; 1.2322x over previous
#include <cuda_runtime.h>
#include <cuda_bf16.h>
#include <cstdint>

// Sparse average pooling, output-driven two-phase:
//   Phase A: zero per-output counters
//   Phase B: invert rulebook into fixed-capacity buckets (atomic slot alloc)
//   Phase C: per-output gather -> accumulate -> single coalesced store
// This writes the 96MB output exactly once (no memset, no output atomics).

#define CAP 32                    // slots per output bucket (Poisson mean 4; 32 = never overflows)
#define NOUT_CAP 400000           // capacity for output rows (problem uses 375000)
#define NRULE_CAP 1600000         // capacity for rules (problem uses 1500000)

__device__ int g_counts[NOUT_CAP];
__device__ int g_bucket[(size_t)NOUT_CAP * CAP];

__global__ void zero_counts_kernel(int n_out)
{
    int i = blockIdx.x * blockDim.x + threadIdx.x;
    if (i < n_out) g_counts[i] = 0;
}

__global__ void bucket_scatter_kernel(const int* __restrict__ rules_in,
                                      const int* __restrict__ rules_out,
                                      int n_rules)
{
    int r = blockIdx.x * blockDim.x + threadIdx.x;
    if (r >= n_rules) return;
    int rout = rules_out[r];
    int slot = atomicAdd(&g_counts[rout], 1);
    if (slot < CAP)
        g_bucket[(size_t)rout * CAP + slot] = rules_in[r];
}

__global__ void gather_kernel(const float* __restrict__ input,
                              float* __restrict__ out,
                              int n_out)
{
    const float scale = 0.125f;   // 1 / POOL_VOLUME

    long long gid = (long long)blockIdx.x * blockDim.x + threadIdx.x;
    int o = (int)(gid >> 4);      // output row
    int c = (int)(gid & 15);      // float4 chunk (0..15)
    if (o >= n_out) return;

    int n = g_counts[o];
    if (n > CAP) n = CAP;

    const int* bk = g_bucket + (size_t)o * CAP;

    float4 acc = make_float4(0.f, 0.f, 0.f, 0.f);
    #pragma unroll 4
    for (int i = 0; i < n; i++) {
        int rin = __ldg(bk + i);
        float4 v = __ldg(reinterpret_cast<const float4*>(input + (size_t)rin * 64) + c);
        acc.x += v.x; acc.y += v.y; acc.z += v.z; acc.w += v.w;
    }
    acc.x *= scale; acc.y *= scale; acc.z *= scale; acc.w *= scale;

    reinterpret_cast<float4*>(out + (size_t)o * 64)[c] = acc;
}

// Fallback path (round-1 atomic scatter) if sizes exceed scratch capacity.
__global__ void avgpool_scatter_kernel(const float* __restrict__ input,
                                       const int* __restrict__ rules_in,
                                       const int* __restrict__ rules_out,
                                       float* __restrict__ out,
                                       int n_rules)
{
    const float scale = 0.125f;
    long long gid = (long long)blockIdx.x * blockDim.x + threadIdx.x;
    long long total = (long long)n_rules * 16;
    if (gid >= total) return;
    int r = (int)(gid >> 4);
    int c = (int)(gid & 15);
    int rin = rules_in[r];
    int rout = rules_out[r];
    const float4* src = reinterpret_cast<const float4*>(input + (long long)rin * 64) + c;
    float4 v = *src;
    v.x *= scale; v.y *= scale; v.z *= scale; v.w *= scale;
    float* dst = out + (long long)rout * 64 + c * 4;
    asm volatile("red.global.add.v4.f32 [%0], {%1, %2, %3, %4};"
                 :: "l"(dst), "f"(v.x), "f"(v.y), "f"(v.z), "f"(v.w) : "memory");
}

extern "C" void kernel_launch(void* const* d_in, const int* in_sizes, int n_in,
                              void* d_out, int out_size)
{
    const float* input     = (const float*)d_in[0];
    const int*   rules_in  = (const int*)d_in[1];
    const int*   rules_out = (const int*)d_in[2];
    float* out = (float*)d_out;

    int n_rules = in_sizes[1];
    int n_out   = out_size / 64;

    if (n_out > NOUT_CAP || n_rules > NRULE_CAP) {
        // Safety fallback: direct atomic scatter
        cudaMemsetAsync(out, 0, (size_t)out_size * sizeof(float));
        long long total = (long long)n_rules * 16;
        int threads = 256;
        long long blocks = (total + threads - 1) / threads;
        avgpool_scatter_kernel<<<(unsigned)blocks, threads>>>(
            input, rules_in, rules_out, out, n_rules);
        return;
    }

    // Phase A: zero counters
    {
        int threads = 256;
        int blocks = (n_out + threads - 1) / threads;
        zero_counts_kernel<<<blocks, threads>>>(n_out);
    }

    // Phase B: invert rulebook into buckets
    {
        int threads = 256;
        int blocks = (n_rules + threads - 1) / threads;
        bucket_scatter_kernel<<<blocks, threads>>>(rules_in, rules_out, n_rules);
    }

    // Phase C: output-driven gather, single write per output row
    {
        long long total = (long long)n_out * 16;
        int threads = 256;
        long long blocks = (total + threads - 1) / threads;
        gather_kernel<<<(unsigned)blocks, threads>>>(input, out, n_out);
    }
}

// round 3
// speedup vs baseline: 1.2782x; 1.0373x over previous
#include <cuda_runtime.h>
#include <cuda_bf16.h>
#include <cstdint>

// Sparse average pooling, output-driven two-phase:
//   Phase A: zero per-output counters (vectorized)
//   Phase B: invert rulebook into fixed-capacity buckets (atomic slot alloc)
//   Phase C: per-output gather with int4 bucket loads (MLP=4) -> one coalesced store
// Output is written exactly once: no memset, no output atomics.

#define CAP 32                    // slots per output bucket (Poisson mean 4)
#define NOUT_CAP 400000
#define NRULE_CAP 1600000

__device__ int g_counts[NOUT_CAP];
__device__ int g_bucket[(size_t)NOUT_CAP * CAP];

__global__ void zero_counts_kernel(int n_words4)
{
    int i = blockIdx.x * blockDim.x + threadIdx.x;
    if (i < n_words4)
        reinterpret_cast<int4*>(g_counts)[i] = make_int4(0, 0, 0, 0);
}

__global__ void bucket_scatter_kernel(const int* __restrict__ rules_in,
                                      const int* __restrict__ rules_out,
                                      int n_rules)
{
    int r = blockIdx.x * blockDim.x + threadIdx.x;
    if (r >= n_rules) return;
    int rout = rules_out[r];
    int slot = atomicAdd(&g_counts[rout], 1);
    if (slot < CAP)
        g_bucket[(size_t)rout * CAP + slot] = rules_in[r];
}

__global__ void gather_kernel(const float* __restrict__ input,
                              float* __restrict__ out,
                              int n_out)
{
    const float scale = 0.125f;   // 1 / POOL_VOLUME

    long long gid = (long long)blockIdx.x * blockDim.x + threadIdx.x;
    int o = (int)(gid >> 4);      // output row
    int c = (int)(gid & 15);      // float4 chunk (0..15)
    if (o >= n_out) return;

    int n = __ldcs(&g_counts[o]);
    if (n > CAP) n = CAP;

    const int4* bk4 = reinterpret_cast<const int4*>(g_bucket + (size_t)o * CAP);
    const float4* in4 = reinterpret_cast<const float4*>(input);

    float4 acc = make_float4(0.f, 0.f, 0.f, 0.f);

    // Process 4 contributing rows per iteration: one 16B index load, then
    // 4 independent 16B gathers (MLP=4 within the group).
    for (int base = 0; base < n; base += 4) {
        int4 idx = __ldcs(bk4 + (base >> 2));
        int m = n - base;

        float4 v0, v1, v2, v3;
        bool p1 = (m > 1), p2 = (m > 2), p3 = (m > 3);
        v0 = __ldg(in4 + (size_t)idx.x * 16 + c);
        if (p1) v1 = __ldg(in4 + (size_t)idx.y * 16 + c);
        if (p2) v2 = __ldg(in4 + (size_t)idx.z * 16 + c);
        if (p3) v3 = __ldg(in4 + (size_t)idx.w * 16 + c);

        acc.x += v0.x; acc.y += v0.y; acc.z += v0.z; acc.w += v0.w;
        if (p1) { acc.x += v1.x; acc.y += v1.y; acc.z += v1.z; acc.w += v1.w; }
        if (p2) { acc.x += v2.x; acc.y += v2.y; acc.z += v2.z; acc.w += v2.w; }
        if (p3) { acc.x += v3.x; acc.y += v3.y; acc.z += v3.z; acc.w += v3.w; }
    }
    acc.x *= scale; acc.y *= scale; acc.z *= scale; acc.w *= scale;

    __stcs(reinterpret_cast<float4*>(out + (size_t)o * 64) + c, acc);
}

// Fallback path (round-1 atomic scatter) if sizes exceed scratch capacity.
__global__ void avgpool_scatter_kernel(const float* __restrict__ input,
                                       const int* __restrict__ rules_in,
                                       const int* __restrict__ rules_out,
                                       float* __restrict__ out,
                                       int n_rules)
{
    const float scale = 0.125f;
    long long gid = (long long)blockIdx.x * blockDim.x + threadIdx.x;
    long long total = (long long)n_rules * 16;
    if (gid >= total) return;
    int r = (int)(gid >> 4);
    int c = (int)(gid & 15);
    int rin = rules_in[r];
    int rout = rules_out[r];
    const float4* src = reinterpret_cast<const float4*>(input + (long long)rin * 64) + c;
    float4 v = *src;
    v.x *= scale; v.y *= scale; v.z *= scale; v.w *= scale;
    float* dst = out + (long long)rout * 64 + c * 4;
    asm volatile("red.global.add.v4.f32 [%0], {%1, %2, %3, %4};"
                 :: "l"(dst), "f"(v.x), "f"(v.y), "f"(v.z), "f"(v.w) : "memory");
}

extern "C" void kernel_launch(void* const* d_in, const int* in_sizes, int n_in,
                              void* d_out, int out_size)
{
    const float* input     = (const float*)d_in[0];
    const int*   rules_in  = (const int*)d_in[1];
    const int*   rules_out = (const int*)d_in[2];
    float* out = (float*)d_out;

    int n_rules = in_sizes[1];
    int n_out   = out_size / 64;

    if (n_out > NOUT_CAP || n_rules > NRULE_CAP) {
        cudaMemsetAsync(out, 0, (size_t)out_size * sizeof(float));
        long long total = (long long)n_rules * 16;
        int threads = 256;
        long long blocks = (total + threads - 1) / threads;
        avgpool_scatter_kernel<<<(unsigned)blocks, threads>>>(
            input, rules_in, rules_out, out, n_rules);
        return;
    }

    // Phase A: zero counters (int4 stores; NOUT_CAP is a multiple of 4)
    {
        int n_words4 = (n_out + 3) / 4;
        int threads = 256;
        int blocks = (n_words4 + threads - 1) / threads;
        zero_counts_kernel<<<blocks, threads>>>(n_words4);
    }

    // Phase B: invert rulebook into buckets
    {
        int threads = 256;
        int blocks = (n_rules + threads - 1) / threads;
        bucket_scatter_kernel<<<blocks, threads>>>(rules_in, rules_out, n_rules);
    }

    // Phase C: output-driven gather, single write per output row
    {
        long long total = (long long)n_out * 16;
        int threads = 256;
        long long blocks = (total + threads - 1) / threads;
        gather_kernel<<<(unsigned)blocks, threads>>>(input, out, n_out);
    }
}